// round 5
// baseline (speedup 1.0000x reference)
#include <cuda_runtime.h>

#define SEQ 100
#define NF  18
#define HD  16
#define TCH 4      // timesteps staged per chunk
#define WPC 8      // warps per CTA
#define BPW 8      // batch per warp
#define BPT 4      // batch per thread

typedef unsigned long long u64;

struct __align__(16) Smem {
    float4 wih1[NF][HD];      // [k][j] = (w_i, w_f, w_g, w_o)
    float4 whh1[HD][HD];
    float4 wih2[HD][HD];
    float4 whh2[HD][HD];
    float4 bias1[HD];
    float4 bias2[HD];
    float2 xs [WPC][TCH][NF][BPW];  // duplicated (v,v)
    float2 h1d[WPC][BPW][HD];       // duplicated (h,h)  (pre-relu, layer1 recurrence)
    float2 h1r[WPC][BPW][HD];       // duplicated relu(h) (layer2 input)
    float2 h2d[WPC][BPW][HD];       // duplicated (h2,h2)
};

__device__ __forceinline__ u64 ffma2(u64 a, u64 b, u64 c) {
    u64 d;
    asm("fma.rn.f32x2 %0, %1, %2, %3;" : "=l"(d) : "l"(a), "l"(b), "l"(c));
    return d;
}
__device__ __forceinline__ float2 unpk(u64 v) {
    float2 r;
    asm("mov.b64 {%0, %1}, %2;" : "=f"(r.x), "=f"(r.y) : "l"(v));
    return r;
}
__device__ __forceinline__ float sigf(float x) {
    float e = __expf(-x);
    return __fdividef(1.f, 1.f + e);
}
// overflow-safe tanh: tanh(x) = sign(x) * (1 - 2/(exp(2|x|)+1))
__device__ __forceinline__ float tanhfast(float x) {
    float a = fabsf(x);
    float e = __expf(2.f * a);
    float t = 1.f - __fdividef(2.f, e + 1.f);
    return x < 0.f ? -t : t;
}

__global__ void __launch_bounds__(256, 2)
lstm2_kernel(const float* __restrict__ x,
             const float* __restrict__ Wih1, const float* __restrict__ Whh1,
             const float* __restrict__ bih1, const float* __restrict__ bhh1,
             const float* __restrict__ Wih2, const float* __restrict__ Whh2,
             const float* __restrict__ bih2, const float* __restrict__ bhh2,
             float* __restrict__ out)
{
    extern __shared__ Smem sm[];
    Smem& s = sm[0];
    const int tid = threadIdx.x;

    // ---- one-time weight prep into smem: [k][j] -> float4 of 4 gates ----
    for (int i = tid; i < NF * HD; i += 256) {
        int k = i >> 4, j = i & 15;
        s.wih1[k][j] = make_float4(Wih1[j * NF + k],        Wih1[(16 + j) * NF + k],
                                   Wih1[(32 + j) * NF + k], Wih1[(48 + j) * NF + k]);
    }
    for (int i = tid; i < HD * HD; i += 256) {
        int k = i >> 4, j = i & 15;
        s.whh1[k][j] = make_float4(Whh1[j * HD + k],        Whh1[(16 + j) * HD + k],
                                   Whh1[(32 + j) * HD + k], Whh1[(48 + j) * HD + k]);
        s.wih2[k][j] = make_float4(Wih2[j * HD + k],        Wih2[(16 + j) * HD + k],
                                   Wih2[(32 + j) * HD + k], Wih2[(48 + j) * HD + k]);
        s.whh2[k][j] = make_float4(Whh2[j * HD + k],        Whh2[(16 + j) * HD + k],
                                   Whh2[(32 + j) * HD + k], Whh2[(48 + j) * HD + k]);
    }
    if (tid < HD) {
        int j = tid;
        s.bias1[j] = make_float4(bih1[j] + bhh1[j],           bih1[16 + j] + bhh1[16 + j],
                                 bih1[32 + j] + bhh1[32 + j], bih1[48 + j] + bhh1[48 + j]);
        s.bias2[j] = make_float4(bih2[j] + bhh2[j],           bih2[16 + j] + bhh2[16 + j],
                                 bih2[32 + j] + bhh2[32 + j], bih2[48 + j] + bhh2[48 + j]);
    }
    __syncthreads();

    const int warp = tid >> 5;
    const int lane = tid & 31;
    const int half = lane >> 4;
    const int j    = lane & 15;
    const int l0   = half * BPT;                       // local batch base (0 or 4)
    const long warpBatch = (long)(blockIdx.x * WPC + warp) * BPW;
    const float* xw = x + warpBatch * (long)(SEQ * NF);

    // init h-state exchange
#pragma unroll
    for (int b = 0; b < BPT; b++) {
        s.h1d[warp][l0 + b][j] = make_float2(0.f, 0.f);
        s.h1r[warp][l0 + b][j] = make_float2(0.f, 0.f);
        s.h2d[warp][l0 + b][j] = make_float2(0.f, 0.f);
    }
    float c1[BPT] = {0.f, 0.f, 0.f, 0.f};
    float c2[BPT] = {0.f, 0.f, 0.f, 0.f};
    float h2v[BPT] = {0.f, 0.f, 0.f, 0.f};
    __syncwarp();

    const ulonglong2 b1 = *reinterpret_cast<const ulonglong2*>(&s.bias1[j]);
    const ulonglong2 b2 = *reinterpret_cast<const ulonglong2*>(&s.bias2[j]);

    for (int t = 0; t < SEQ; t++) {
        const int tt = t & (TCH - 1);
        if (tt == 0) {
            // stage TCH steps of x for this warp's 8 batches, duplicated
            for (int idx = lane; idx < TCH * BPW * NF; idx += 32) {
                int k  = idx % NF;
                int tb = idx / NF;          // (tc*8 + b), k fastest -> coalesced-ish
                int b  = tb & 7;
                int tc = tb >> 3;
                float v = xw[(long)b * (SEQ * NF) + (t + tc) * NF + k];
                s.xs[warp][tc][k][b] = make_float2(v, v);
            }
            __syncwarp();
        }

        // ================= layer 1 =================
        u64 aif[BPT], ago[BPT];
#pragma unroll
        for (int b = 0; b < BPT; b++) { aif[b] = b1.x; ago[b] = b1.y; }

#pragma unroll
        for (int k = 0; k < NF; k++) {
            ulonglong2 w = *reinterpret_cast<const ulonglong2*>(&s.wih1[k][j]);
#pragma unroll
            for (int b = 0; b < BPT; b++) {
                u64 xv = *reinterpret_cast<const u64*>(&s.xs[warp][tt][k][l0 + b]);
                aif[b] = ffma2(xv, w.x, aif[b]);
                ago[b] = ffma2(xv, w.y, ago[b]);
            }
        }
#pragma unroll
        for (int k = 0; k < HD; k++) {
            ulonglong2 w = *reinterpret_cast<const ulonglong2*>(&s.whh1[k][j]);
#pragma unroll
            for (int b = 0; b < BPT; b++) {
                u64 hv = *reinterpret_cast<const u64*>(&s.h1d[warp][l0 + b][k]);
                aif[b] = ffma2(hv, w.x, aif[b]);
                ago[b] = ffma2(hv, w.y, ago[b]);
            }
        }
        float h1v[BPT];
#pragma unroll
        for (int b = 0; b < BPT; b++) {
            float2 vif = unpk(aif[b]);
            float2 vgo = unpk(ago[b]);
            float ig = sigf(vif.x);
            float fg = sigf(vif.y);
            float gg = tanhfast(vgo.x);
            float og = sigf(vgo.y);
            float c  = fmaf(fg, c1[b], ig * gg);
            c1[b]    = c;
            h1v[b]   = og * tanhfast(c);
        }
        __syncwarp();   // everyone done reading old h1d
#pragma unroll
        for (int b = 0; b < BPT; b++) {
            float h = h1v[b];
            s.h1d[warp][l0 + b][j] = make_float2(h, h);
            float r = fmaxf(h, 0.f);
            s.h1r[warp][l0 + b][j] = make_float2(r, r);
        }
        __syncwarp();   // new h1 visible

        // ================= layer 2 =================
#pragma unroll
        for (int b = 0; b < BPT; b++) { aif[b] = b2.x; ago[b] = b2.y; }

#pragma unroll
        for (int k = 0; k < HD; k++) {
            ulonglong2 w = *reinterpret_cast<const ulonglong2*>(&s.wih2[k][j]);
#pragma unroll
            for (int b = 0; b < BPT; b++) {
                u64 hv = *reinterpret_cast<const u64*>(&s.h1r[warp][l0 + b][k]);
                aif[b] = ffma2(hv, w.x, aif[b]);
                ago[b] = ffma2(hv, w.y, ago[b]);
            }
        }
#pragma unroll
        for (int k = 0; k < HD; k++) {
            ulonglong2 w = *reinterpret_cast<const ulonglong2*>(&s.whh2[k][j]);
#pragma unroll
            for (int b = 0; b < BPT; b++) {
                u64 hv = *reinterpret_cast<const u64*>(&s.h2d[warp][l0 + b][k]);
                aif[b] = ffma2(hv, w.x, aif[b]);
                ago[b] = ffma2(hv, w.y, ago[b]);
            }
        }
#pragma unroll
        for (int b = 0; b < BPT; b++) {
            float2 vif = unpk(aif[b]);
            float2 vgo = unpk(ago[b]);
            float ig = sigf(vif.x);
            float fg = sigf(vif.y);
            float gg = tanhfast(vgo.x);
            float og = sigf(vgo.y);
            float c  = fmaf(fg, c2[b], ig * gg);
            c2[b]    = c;
            h2v[b]   = og * tanhfast(c);
        }
        __syncwarp();   // everyone done reading old h2d
#pragma unroll
        for (int b = 0; b < BPT; b++) {
            float h = h2v[b];
            s.h2d[warp][l0 + b][j] = make_float2(h, h);
        }
        __syncwarp();   // new h2 visible
    }

    // ---- output: relu(h2_last), [B, 16] ----
#pragma unroll
    for (int b = 0; b < BPT; b++) {
        out[(warpBatch + l0 + b) * HD + j] = fmaxf(h2v[b], 0.f);
    }
}

extern "C" void kernel_launch(void* const* d_in, const int* in_sizes, int n_in,
                              void* d_out, int out_size)
{
    const float* x    = (const float*)d_in[0];
    const float* Wih1 = (const float*)d_in[1];
    const float* Whh1 = (const float*)d_in[2];
    const float* bih1 = (const float*)d_in[3];
    const float* bhh1 = (const float*)d_in[4];
    const float* Wih2 = (const float*)d_in[5];
    const float* Whh2 = (const float*)d_in[6];
    const float* bih2 = (const float*)d_in[7];
    const float* bhh2 = (const float*)d_in[8];
    float* out = (float*)d_out;

    const int smem = (int)sizeof(Smem);   // ~78.8 KB -> needs opt-in
    cudaFuncSetAttribute(lstm2_kernel,
                         cudaFuncAttributeMaxDynamicSharedMemorySize, smem);

    // 16384 batch / (8 warps * 8 batch) = 256 CTAs of 256 threads
    lstm2_kernel<<<256, 256, smem>>>(x, Wih1, Whh1, bih1, bhh1,
                                     Wih2, Whh2, bih2, bhh2, out);
}